// round 2
// baseline (speedup 1.0000x reference)
#include <cuda_runtime.h>
#include <math.h>

// Problem constants
#define BB 32      // batch
#define SS 128     // steps (sequence)
#define NC 128     // NUM_CAPSULE
#define DD 64      // DIM_CAPSULE
#define II 256     // in_dim
#define OD 8192    // NC*DD

// Scratch (device globals: no allocations allowed)
__device__ float g_PE1[NC * DD];        // [n][d]
__device__ float g_PE2[SS * OD];        // [s][n*64+d]  (4 MB)
__device__ float g_P  [BB * SS * DD];   // [b][s][d]
__device__ float g_Su [BB * SS];        // [b][s]
__device__ float g_C  [BB * NC * SS];   // coupling c[b][n][s]
__device__ float g_T  [BB * NC * DD];   // pre-squash partial (terms 1+2)
__device__ float g_V  [BB * NC * DD];   // outputs v[b][n][d]
__device__ float g_Bl [BB * NC * SS];   // routing logits b[b][n][s]

// ---------------------------------------------------------------------------
// Sinusoid tables: PE2[s, 2k]=sin(s*f2k), PE2[s,2k+1]=cos(s*f2k), f2k=10000^(-k/4096)
// PE1 same with D=64 (f = 10000^(-k/32)). One block per s (128 blocks).
// ---------------------------------------------------------------------------
__global__ void k_tables() {
    int s = blockIdx.x;
    const float LN1E4 = 9.210340371976184f;
    for (int k = threadIdx.x; k < OD / 2; k += blockDim.x) {
        float invf = expf(-(float)k * (LN1E4 / 4096.0f));
        float ang = (float)s * invf;
        float sv, cv;
        sincosf(ang, &sv, &cv);
        g_PE2[s * OD + 2 * k]     = sv;
        g_PE2[s * OD + 2 * k + 1] = cv;
    }
    for (int k = threadIdx.x; k < DD / 2; k += blockDim.x) {
        float invf = expf(-(float)k * (LN1E4 / 32.0f));
        float ang = (float)s * invf;
        float sv, cv;
        sincosf(ang, &sv, &cv);
        g_PE1[s * DD + 2 * k]     = sv;
        g_PE1[s * DD + 2 * k + 1] = cv;
    }
}

// ---------------------------------------------------------------------------
// P[b,s,d] = sum_i u[b,s,i]*W[i,d];  Su[b,s] = sum_i u[b,s,i]
// Block handles 16 consecutive (b,s) rows. 256 threads.
// ---------------------------------------------------------------------------
__global__ void k_gemmP(const float* __restrict__ u, const float* __restrict__ W) {
    __shared__ float shU[16][II];  // 16 KB
    int row0 = blockIdx.x * 16;    // global row in [0, BB*SS)
    for (int idx = threadIdx.x; idx < 16 * II; idx += 256) {
        int r = idx / II, i = idx % II;
        shU[r][i] = u[(row0 + r) * II + i];
    }
    __syncthreads();
    int d = threadIdx.x & 63;
    int g = threadIdx.x >> 6;  // 0..3 -> rows g, g+4, g+8, g+12
    float a0 = 0.f, a1 = 0.f, a2 = 0.f, a3 = 0.f;
    #pragma unroll 4
    for (int i = 0; i < II; i++) {
        float w = W[i * DD + d];
        a0 += shU[g][i]      * w;
        a1 += shU[g + 4][i]  * w;
        a2 += shU[g + 8][i]  * w;
        a3 += shU[g + 12][i] * w;
    }
    g_P[(row0 + g) * DD + d]      = a0;
    g_P[(row0 + g + 4) * DD + d]  = a1;
    g_P[(row0 + g + 8) * DD + d]  = a2;
    g_P[(row0 + g + 12) * DD + d] = a3;
    __syncthreads();
    if (threadIdx.x < 16) {
        float t = 0.f;
        for (int i = 0; i < II; i++) t += shU[threadIdx.x][i];
        g_Su[row0 + threadIdx.x] = t;
    }
}

// ---------------------------------------------------------------------------
// Initial coupling: c[b,n,s] = mask[b,s] / 128  (softmax of zeros * mask)
// ---------------------------------------------------------------------------
__global__ void k_initC(const float* __restrict__ mask) {
    int idx = blockIdx.x * blockDim.x + threadIdx.x;
    if (idx < BB * NC * SS) {
        int s = idx & (SS - 1);
        int b = idx / (NC * SS);
        g_C[idx] = mask[b * SS + s] * (1.0f / 128.0f);
    }
}

// ---------------------------------------------------------------------------
// Output terms 1+2: T[b,n,d] = sum_s c[b,n,s]*P[b,s,d] + (sum_s c*Su)*PE1[n,d]
// Block = (b, 16-n tile). Groups of 64 threads each own 4 consecutive n.
// ---------------------------------------------------------------------------
__global__ void k_outA() {
    __shared__ float shP[SS * DD];   // 32 KB, [s*64+d] (d-varying access: no conflicts)
    __shared__ float shC[16 * SS];   // 8 KB
    __shared__ float shSu[SS];
    int b = blockIdx.x >> 3, n0 = (blockIdx.x & 7) * 16;
    for (int idx = threadIdx.x; idx < SS * DD; idx += 256)
        shP[idx] = g_P[b * SS * DD + idx];
    for (int idx = threadIdx.x; idx < 16 * SS; idx += 256)
        shC[idx] = g_C[(b * NC + n0) * SS + idx];
    if (threadIdx.x < SS) shSu[threadIdx.x] = g_Su[b * SS + threadIdx.x];
    __syncthreads();
    int d = threadIdx.x & 63, g = threadIdx.x >> 6;
    const float* c0 = &shC[(g * 4 + 0) * SS];
    const float* c1 = &shC[(g * 4 + 1) * SS];
    const float* c2 = &shC[(g * 4 + 2) * SS];
    const float* c3 = &shC[(g * 4 + 3) * SS];
    float a0 = 0, a1 = 0, a2 = 0, a3 = 0, q0 = 0, q1 = 0, q2 = 0, q3 = 0;
    #pragma unroll 4
    for (int s = 0; s < SS; s++) {
        float p = shP[s * DD + d];
        float su = shSu[s];
        float v0 = c0[s], v1 = c1[s], v2 = c2[s], v3 = c3[s];
        a0 += v0 * p;  a1 += v1 * p;  a2 += v2 * p;  a3 += v3 * p;
        q0 += v0 * su; q1 += v1 * su; q2 += v2 * su; q3 += v3 * su;
    }
    int nb = n0 + g * 4;
    g_T[(b * NC + nb + 0) * DD + d] = a0 + q0 * g_PE1[(nb + 0) * DD + d];
    g_T[(b * NC + nb + 1) * DD + d] = a1 + q1 * g_PE1[(nb + 1) * DD + d];
    g_T[(b * NC + nb + 2) * DD + d] = a2 + q2 * g_PE1[(nb + 2) * DD + d];
    g_T[(b * NC + nb + 3) * DD + d] = a3 + q3 * g_PE1[(nb + 3) * DD + d];
}

// ---------------------------------------------------------------------------
// Output term 3 + squash: val = T + sum_s c[b,n,s]*PE2[s, n*64+d]; V = squash(val)
// Block per n (128 blocks). b processed 16 at a time (two smem passes).
// ---------------------------------------------------------------------------
__global__ void k_outB(float* __restrict__ dst, int final_) {
    __shared__ float shPE2[SS * DD];  // 32 KB
    __shared__ float shC[16 * SS];    // 8 KB
    __shared__ float shRed[4][2];
    float* Vout = final_ ? dst : g_V;
    int n = blockIdx.x;
    for (int idx = threadIdx.x; idx < SS * DD; idx += 256) {
        int s = idx >> 6, d = idx & 63;
        shPE2[idx] = g_PE2[s * OD + n * DD + d];
    }
    int d = threadIdx.x & 63, g = threadIdx.x >> 6;
    int lane = threadIdx.x & 31, wig = (threadIdx.x >> 5) & 1;
    for (int bh = 0; bh < 2; bh++) {
        __syncthreads();
        for (int idx = threadIdx.x; idx < 16 * SS; idx += 256) {
            int bl = idx >> 7, s2 = idx & 127;
            shC[idx] = g_C[((bh * 16 + bl) * NC + n) * SS + s2];
        }
        __syncthreads();
        const float* c0 = &shC[(g * 4 + 0) * SS];
        const float* c1 = &shC[(g * 4 + 1) * SS];
        const float* c2 = &shC[(g * 4 + 2) * SS];
        const float* c3 = &shC[(g * 4 + 3) * SS];
        float acc[4] = {0.f, 0.f, 0.f, 0.f};
        #pragma unroll 4
        for (int s = 0; s < SS; s++) {
            float p = shPE2[s * DD + d];
            acc[0] += c0[s] * p; acc[1] += c1[s] * p;
            acc[2] += c2[s] * p; acc[3] += c3[s] * p;
        }
        int bbase = bh * 16 + g * 4;
        #pragma unroll
        for (int j = 0; j < 4; j++) {
            int b = bbase + j;
            float val = g_T[(b * NC + n) * DD + d] + acc[j];
            float ss = val * val;
            #pragma unroll
            for (int off = 16; off; off >>= 1)
                ss += __shfl_xor_sync(0xffffffffu, ss, off);
            if (lane == 0) shRed[g][wig] = ss;
            __syncthreads();
            float sst = shRed[g][0] + shRed[g][1];
            __syncthreads();
            float sc = sst / (1.0f + sst) * rsqrtf(sst + 1e-7f);
            Vout[(b * NC + n) * DD + d] = sc * val;
        }
    }
}

// ---------------------------------------------------------------------------
// Logit terms 1+2: Bl[b,n,s] = sum_d v[b,n,d]*P[b,s,d] + Su[b,s]*(v[b,n,:].PE1[n,:])
// Block = (b, 32-n tile). Thread owns one s; processes n 4 at a time.
// shP pitched to 65 floats: per-thread s is fixed, d varies -> avoids 32-way conflicts.
// ---------------------------------------------------------------------------
__global__ void k_bA() {
    __shared__ float shP[SS * 65];   // 33.3 KB
    __shared__ float shV[32 * DD];   // 8 KB
    __shared__ float shSu[SS];
    __shared__ float shSc[32];
    int b = blockIdx.x >> 2, n0 = (blockIdx.x & 3) * 32;
    for (int idx = threadIdx.x; idx < SS * DD; idx += 256) {
        int s = idx >> 6, dd = idx & 63;
        shP[s * 65 + dd] = g_P[b * SS * DD + idx];
    }
    for (int idx = threadIdx.x; idx < 32 * DD; idx += 256)
        shV[idx] = g_V[(b * NC + n0) * DD + idx];
    if (threadIdx.x < SS) shSu[threadIdx.x] = g_Su[b * SS + threadIdx.x];
    __syncthreads();
    if (threadIdx.x < 32) {
        int nl = threadIdx.x;
        const float* pe = &g_PE1[(n0 + nl) * DD];
        const float* vv = &shV[nl * DD];
        float t = 0.f;
        for (int dd = 0; dd < DD; dd++) t += vv[dd] * pe[dd];
        shSc[nl] = t;
    }
    __syncthreads();
    int s = threadIdx.x & 127, h = threadIdx.x >> 7;
    const float* pr = &shP[s * 65];
    float su = shSu[s];
    for (int nq = 0; nq < 4; nq++) {
        int nl = h * 16 + nq * 4;
        const float* v0 = &shV[(nl + 0) * DD];
        const float* v1 = &shV[(nl + 1) * DD];
        const float* v2 = &shV[(nl + 2) * DD];
        const float* v3 = &shV[(nl + 3) * DD];
        float a0 = 0, a1 = 0, a2 = 0, a3 = 0;
        #pragma unroll 8
        for (int dd = 0; dd < DD; dd++) {
            float p = pr[dd];
            a0 += v0[dd] * p; a1 += v1[dd] * p;
            a2 += v2[dd] * p; a3 += v3[dd] * p;
        }
        g_Bl[(b * NC + n0 + nl + 0) * SS + s] = a0 + su * shSc[nl + 0];
        g_Bl[(b * NC + n0 + nl + 1) * SS + s] = a1 + su * shSc[nl + 1];
        g_Bl[(b * NC + n0 + nl + 2) * SS + s] = a2 + su * shSc[nl + 2];
        g_Bl[(b * NC + n0 + nl + 3) * SS + s] = a3 + su * shSc[nl + 3];
    }
}

// ---------------------------------------------------------------------------
// Logit term 3: Bl[b,n,s] += sum_d v[b,n,d]*PE2[s, n*64+d]. Block per n.
// ---------------------------------------------------------------------------
__global__ void k_bB() {
    __shared__ float shPE2[SS * 65];  // 33.3 KB (pitched: s fixed per thread, d varies)
    __shared__ float shV[32 * DD];    // 8 KB
    int n = blockIdx.x;
    for (int idx = threadIdx.x; idx < SS * DD; idx += 256) {
        int s = idx >> 6, dd = idx & 63;
        shPE2[s * 65 + dd] = g_PE2[s * OD + n * DD + dd];
    }
    for (int idx = threadIdx.x; idx < 32 * DD; idx += 256) {
        int bl = idx >> 6, dd = idx & 63;
        shV[idx] = g_V[(bl * NC + n) * DD + dd];
    }
    __syncthreads();
    int s = threadIdx.x & 127, h = threadIdx.x >> 7;
    const float* pr = &shPE2[s * 65];
    for (int bq = 0; bq < 4; bq++) {
        int bl = h * 16 + bq * 4;
        const float* v0 = &shV[(bl + 0) * DD];
        const float* v1 = &shV[(bl + 1) * DD];
        const float* v2 = &shV[(bl + 2) * DD];
        const float* v3 = &shV[(bl + 3) * DD];
        float a0 = 0, a1 = 0, a2 = 0, a3 = 0;
        #pragma unroll 8
        for (int dd = 0; dd < DD; dd++) {
            float p = pr[dd];
            a0 += v0[dd] * p; a1 += v1[dd] * p;
            a2 += v2[dd] * p; a3 += v3[dd] * p;
        }
        g_Bl[((bl + 0) * NC + n) * SS + s] += a0;
        g_Bl[((bl + 1) * NC + n) * SS + s] += a1;
        g_Bl[((bl + 2) * NC + n) * SS + s] += a2;
        g_Bl[((bl + 3) * NC + n) * SS + s] += a3;
    }
}

// ---------------------------------------------------------------------------
// c[b,n,s] = softmax over n of Bl[b,:,s] (max-subtracted) * mask[b,s]
// Block = (b, 32-s tile), 32 threads (one s per lane).
// ---------------------------------------------------------------------------
__global__ void k_softmax(const float* __restrict__ mask) {
    __shared__ float shE[NC * 33];  // 16.9 KB, [n*33 + lane]
    int b = blockIdx.x >> 2, s0 = (blockIdx.x & 3) * 32;
    int lane = threadIdx.x;
    int s = s0 + lane;
    float mx = -1e30f;
    for (int nn = 0; nn < NC; nn++) {
        float v = g_Bl[(b * NC + nn) * SS + s];
        shE[nn * 33 + lane] = v;
        mx = fmaxf(mx, v);
    }
    float sum = 0.f;
    for (int nn = 0; nn < NC; nn++) {
        float e = expf(shE[nn * 33 + lane] - mx);
        shE[nn * 33 + lane] = e;
        sum += e;
    }
    float scale = mask[b * SS + s] / sum;
    for (int nn = 0; nn < NC; nn++)
        g_C[(b * NC + nn) * SS + s] = shE[nn * 33 + lane] * scale;
}

// ---------------------------------------------------------------------------
extern "C" void kernel_launch(void* const* d_in, const int* in_sizes, int n_in,
                              void* d_out, int out_size) {
    const float* u    = (const float*)d_in[0];  // (32,128,256)
    const float* mask = (const float*)d_in[1];  // (32,128)
    const float* W    = (const float*)d_in[2];  // (1,256,64)
    float* out = (float*)d_out;                 // (32,128,64)

    k_tables<<<SS, 256>>>();
    k_gemmP<<<(BB * SS) / 16, 256>>>(u, W);
    k_initC<<<(BB * NC * SS + 255) / 256, 256>>>(mask);

    for (int it = 0; it < 3; it++) {
        k_outA<<<BB * 8, 256>>>();
        k_outB<<<NC, 256>>>(out, it == 2 ? 1 : 0);
        if (it < 2) {
            k_bA<<<BB * 4, 256>>>();
            k_bB<<<NC, 256>>>();
            k_softmax<<<BB * 4, 32>>>(mask);
        }
    }
}

// round 4
// speedup vs baseline: 1.3636x; 1.3636x over previous
#include <cuda_runtime.h>
#include <math.h>

#define BB 32
#define SS 128
#define NC 128
#define DD 64
#define II 256
#define OD 8192   // NC*DD
#define TOFF (BB*NC*DD)

__device__ float g_PE1[NC * DD];
__device__ float g_PE2[SS * OD];        // 4 MB
__device__ float g_P  [BB * SS * DD];
__device__ float g_Su [BB * SS];
__device__ float g_C  [BB * NC * SS];
__device__ float g_T  [2 * BB * NC * DD];  // two s-halves of the partial output
__device__ float g_V  [BB * NC * DD];
__device__ float g_Bl [BB * NC * SS];

// ---------------------------------------------------------------------------
// Tables + initial coupling. 512 blocks: s = blk>>2, k-chunk = blk&3.
// ---------------------------------------------------------------------------
__global__ void __launch_bounds__(256) k_tables(const float* __restrict__ mask) {
    const float LN1E4 = 9.210340371976184f;
    int s = blockIdx.x >> 2;
    int chunk = blockIdx.x & 3;
    int base = chunk * 1024;
    #pragma unroll
    for (int j = 0; j < 4; j++) {
        int k = base + j * 256 + threadIdx.x;
        float invf = __expf(-(float)k * (LN1E4 / 4096.0f));
        float sv, cv;
        __sincosf((float)s * invf, &sv, &cv);
        g_PE2[s * OD + 2 * k]     = sv;
        g_PE2[s * OD + 2 * k + 1] = cv;
    }
    if (chunk == 0 && threadIdx.x < 32) {
        int k = threadIdx.x;
        float invf = __expf(-(float)k * (LN1E4 / 32.0f));
        float sv, cv;
        __sincosf((float)s * invf, &sv, &cv);
        g_PE1[s * DD + 2 * k]     = sv;
        g_PE1[s * DD + 2 * k + 1] = cv;
    }
    // fused initC: c = mask/128
    for (int idx = blockIdx.x * 256 + threadIdx.x; idx < BB * NC * SS;
         idx += gridDim.x * 256) {
        int s2 = idx & (SS - 1);
        int b  = idx >> 14;            // / (NC*SS)
        g_C[idx] = mask[b * SS + s2] * (1.0f / 128.0f);
    }
}

// ---------------------------------------------------------------------------
// P[b,s,d] = sum_i u[row,i]*W[i,d];  Su[row] = sum_i u[row,i]
// ---------------------------------------------------------------------------
__global__ void __launch_bounds__(256) k_gemmP(const float* __restrict__ u,
                                               const float* __restrict__ W) {
    __shared__ float shU[16][II];
    int row0 = blockIdx.x * 16;
    for (int idx = threadIdx.x; idx < 16 * II; idx += 256) {
        int r = idx >> 8, i = idx & 255;
        shU[r][i] = u[(row0 + r) * II + i];
    }
    __syncthreads();
    int d = threadIdx.x & 63, g = threadIdx.x >> 6;
    const float4* u0 = (const float4*)&shU[g][0];
    const float4* u1 = (const float4*)&shU[g + 4][0];
    const float4* u2 = (const float4*)&shU[g + 8][0];
    const float4* u3 = (const float4*)&shU[g + 12][0];
    float a0 = 0, a1 = 0, a2 = 0, a3 = 0;
    #pragma unroll 8
    for (int i4 = 0; i4 < II / 4; i4++) {
        float4 f0 = u0[i4], f1 = u1[i4], f2 = u2[i4], f3 = u3[i4];
        float w0 = __ldg(&W[(i4 * 4 + 0) * DD + d]);
        float w1 = __ldg(&W[(i4 * 4 + 1) * DD + d]);
        float w2 = __ldg(&W[(i4 * 4 + 2) * DD + d]);
        float w3 = __ldg(&W[(i4 * 4 + 3) * DD + d]);
        a0 += f0.x * w0 + f0.y * w1 + f0.z * w2 + f0.w * w3;
        a1 += f1.x * w0 + f1.y * w1 + f1.z * w2 + f1.w * w3;
        a2 += f2.x * w0 + f2.y * w1 + f2.z * w2 + f2.w * w3;
        a3 += f3.x * w0 + f3.y * w1 + f3.z * w2 + f3.w * w3;
    }
    g_P[(row0 + g) * DD + d]      = a0;
    g_P[(row0 + g + 4) * DD + d]  = a1;
    g_P[(row0 + g + 8) * DD + d]  = a2;
    g_P[(row0 + g + 12) * DD + d] = a3;
    // Su: 16 lanes per row, shuffle reduce
    int r = threadIdx.x >> 4, t = threadIdx.x & 15;
    float sm = 0.f;
    for (int i = t; i < II; i += 16) sm += shU[r][i];
    sm += __shfl_xor_sync(0xffffffffu, sm, 8);
    sm += __shfl_xor_sync(0xffffffffu, sm, 4);
    sm += __shfl_xor_sync(0xffffffffu, sm, 2);
    sm += __shfl_xor_sync(0xffffffffu, sm, 1);
    if (t == 0) g_Su[row0 + r] = sm;
}

// ---------------------------------------------------------------------------
// Output terms 1+2, s-split in halves:
// T[half][b,n,d] = sum_{s in half} c*P + (sum_{s in half} c*Su)*PE1[n,d]
// grid = 32 b * 8 ntile * 2 half = 512
// ---------------------------------------------------------------------------
__global__ void __launch_bounds__(256) k_outA() {
    __shared__ float  shP[64 * DD];     // 16 KB (half of P_b)
    __shared__ float4 shC4[16 * 16];    // 16 n x 64 s
    __shared__ float4 shSu4[16];
    int blk  = blockIdx.x;
    int half = blk & 1;
    int n0   = ((blk >> 1) & 7) * 16;
    int b    = blk >> 4;
    int sb   = half * 64;
    for (int idx = threadIdx.x; idx < 64 * DD; idx += 256)
        shP[idx] = g_P[(b * SS + sb) * DD + idx];
    for (int idx = threadIdx.x; idx < 16 * 16; idx += 256) {
        int nr = idx >> 4, sc = idx & 15;
        shC4[idx] = *(const float4*)&g_C[(b * NC + n0 + nr) * SS + sb + sc * 4];
    }
    if (threadIdx.x < 16)
        shSu4[threadIdx.x] = *(const float4*)&g_Su[b * SS + sb + threadIdx.x * 4];
    __syncthreads();
    int d = threadIdx.x & 63, g = threadIdx.x >> 6;
    const float4* c0 = &shC4[(g * 4 + 0) * 16];
    const float4* c1 = &shC4[(g * 4 + 1) * 16];
    const float4* c2 = &shC4[(g * 4 + 2) * 16];
    const float4* c3 = &shC4[(g * 4 + 3) * 16];
    float a0 = 0, a1 = 0, a2 = 0, a3 = 0, q0 = 0, q1 = 0, q2 = 0, q3 = 0;
    #pragma unroll
    for (int s4 = 0; s4 < 16; s4++) {
        float4 f0 = c0[s4], f1 = c1[s4], f2 = c2[s4], f3 = c3[s4];
        float4 su = shSu4[s4];
        float p0 = shP[(s4 * 4 + 0) * DD + d];
        float p1 = shP[(s4 * 4 + 1) * DD + d];
        float p2 = shP[(s4 * 4 + 2) * DD + d];
        float p3 = shP[(s4 * 4 + 3) * DD + d];
        a0 += f0.x * p0 + f0.y * p1 + f0.z * p2 + f0.w * p3;
        a1 += f1.x * p0 + f1.y * p1 + f1.z * p2 + f1.w * p3;
        a2 += f2.x * p0 + f2.y * p1 + f2.z * p2 + f2.w * p3;
        a3 += f3.x * p0 + f3.y * p1 + f3.z * p2 + f3.w * p3;
        q0 += f0.x * su.x + f0.y * su.y + f0.z * su.z + f0.w * su.w;
        q1 += f1.x * su.x + f1.y * su.y + f1.z * su.z + f1.w * su.w;
        q2 += f2.x * su.x + f2.y * su.y + f2.z * su.z + f2.w * su.w;
        q3 += f3.x * su.x + f3.y * su.y + f3.z * su.z + f3.w * su.w;
    }
    int nb = n0 + g * 4;
    float* T = g_T + half * TOFF;
    T[(b * NC + nb + 0) * DD + d] = a0 + q0 * g_PE1[(nb + 0) * DD + d];
    T[(b * NC + nb + 1) * DD + d] = a1 + q1 * g_PE1[(nb + 1) * DD + d];
    T[(b * NC + nb + 2) * DD + d] = a2 + q2 * g_PE1[(nb + 2) * DD + d];
    T[(b * NC + nb + 3) * DD + d] = a3 + q3 * g_PE1[(nb + 3) * DD + d];
}

// ---------------------------------------------------------------------------
// Output term 3 + squash. grid = 128 n * 4 btile = 512; 8 b per block.
// ---------------------------------------------------------------------------
__global__ void __launch_bounds__(256) k_outB(float* __restrict__ dst, int final_) {
    __shared__ float  shPE2[SS * DD];   // 32 KB
    __shared__ float4 shC4[8 * 32];     // 8 b x 128 s
    __shared__ float  shRed[4][2][2];
    int n  = blockIdx.x >> 2;
    int b0 = (blockIdx.x & 3) * 8;
    float* Vout = final_ ? dst : g_V;
    for (int idx = threadIdx.x; idx < SS * DD; idx += 256) {
        int s = idx >> 6, d = idx & 63;
        shPE2[idx] = g_PE2[s * OD + n * DD + d];
    }
    for (int idx = threadIdx.x; idx < 8 * 32; idx += 256) {
        int bl = idx >> 5, sc = idx & 31;
        shC4[idx] = *(const float4*)&g_C[((b0 + bl) * NC + n) * SS + sc * 4];
    }
    __syncthreads();
    int d = threadIdx.x & 63, g = threadIdx.x >> 6;
    int lane = threadIdx.x & 31, wig = (threadIdx.x >> 5) & 1;
    const float4* c0 = &shC4[(g * 2 + 0) * 32];
    const float4* c1 = &shC4[(g * 2 + 1) * 32];
    float a0 = 0, a1 = 0;
    #pragma unroll
    for (int s4 = 0; s4 < 32; s4++) {
        float4 f0 = c0[s4], f1 = c1[s4];
        float p0 = shPE2[(s4 * 4 + 0) * DD + d];
        float p1 = shPE2[(s4 * 4 + 1) * DD + d];
        float p2 = shPE2[(s4 * 4 + 2) * DD + d];
        float p3 = shPE2[(s4 * 4 + 3) * DD + d];
        a0 += f0.x * p0 + f0.y * p1 + f0.z * p2 + f0.w * p3;
        a1 += f1.x * p0 + f1.y * p1 + f1.z * p2 + f1.w * p3;
    }
    int bA = b0 + g * 2, bBd = bA + 1;
    float val0 = g_T[(bA * NC + n) * DD + d] + g_T[TOFF + (bA * NC + n) * DD + d] + a0;
    float val1 = g_T[(bBd * NC + n) * DD + d] + g_T[TOFF + (bBd * NC + n) * DD + d] + a1;
    float ss0 = val0 * val0, ss1 = val1 * val1;
    #pragma unroll
    for (int off = 16; off; off >>= 1) {
        ss0 += __shfl_xor_sync(0xffffffffu, ss0, off);
        ss1 += __shfl_xor_sync(0xffffffffu, ss1, off);
    }
    if (lane == 0) { shRed[g][wig][0] = ss0; shRed[g][wig][1] = ss1; }
    __syncthreads();
    float t0 = shRed[g][0][0] + shRed[g][1][0];
    float t1 = shRed[g][0][1] + shRed[g][1][1];
    float sc0 = t0 / (1.0f + t0) * rsqrtf(t0 + 1e-7f);
    float sc1 = t1 / (1.0f + t1) * rsqrtf(t1 + 1e-7f);
    Vout[(bA  * NC + n) * DD + d] = sc0 * val0;
    Vout[(bBd * NC + n) * DD + d] = sc1 * val1;
}

// ---------------------------------------------------------------------------
// Logit terms 1+2. grid = 32 b * 16 ntile = 512; 8 n per block.
// shP pitched to 68 floats for conflict-free lane-stride LDS.128.
// ---------------------------------------------------------------------------
__global__ void __launch_bounds__(256) k_bA() {
    __shared__ float shP[SS * 68];   // 34.8 KB
    __shared__ float shV[8 * DD];
    __shared__ float shSu[SS];
    __shared__ float shSc[8];
    int b  = blockIdx.x >> 4;
    int n0 = (blockIdx.x & 15) * 8;
    for (int idx = threadIdx.x; idx < SS * 16; idx += 256) {
        int s = idx >> 4, c = idx & 15;
        *(float4*)&shP[s * 68 + c * 4] = *(const float4*)&g_P[(b * SS + s) * DD + c * 4];
    }
    for (int idx = threadIdx.x; idx < 8 * DD; idx += 256)
        shV[idx] = g_V[(b * NC + n0) * DD + idx];
    if (threadIdx.x < SS) shSu[threadIdx.x] = g_Su[b * SS + threadIdx.x];
    __syncthreads();
    if (threadIdx.x < 8) {
        int nl = threadIdx.x;
        float t = 0.f;
        for (int dd = 0; dd < DD; dd++) t += shV[nl * DD + dd] * g_PE1[(n0 + nl) * DD + dd];
        shSc[nl] = t;
    }
    __syncthreads();
    int s = threadIdx.x & 127, h = threadIdx.x >> 7;
    int nl = h * 4;
    const float4* pr = (const float4*)&shP[s * 68];
    const float4* v0 = (const float4*)&shV[(nl + 0) * DD];
    const float4* v1 = (const float4*)&shV[(nl + 1) * DD];
    const float4* v2 = (const float4*)&shV[(nl + 2) * DD];
    const float4* v3 = (const float4*)&shV[(nl + 3) * DD];
    float a0 = 0, a1 = 0, a2 = 0, a3 = 0;
    #pragma unroll
    for (int d4 = 0; d4 < 16; d4++) {
        float4 p = pr[d4];
        float4 w0 = v0[d4], w1 = v1[d4], w2 = v2[d4], w3 = v3[d4];
        a0 += p.x * w0.x + p.y * w0.y + p.z * w0.z + p.w * w0.w;
        a1 += p.x * w1.x + p.y * w1.y + p.z * w1.z + p.w * w1.w;
        a2 += p.x * w2.x + p.y * w2.y + p.z * w2.z + p.w * w2.w;
        a3 += p.x * w3.x + p.y * w3.y + p.z * w3.z + p.w * w3.w;
    }
    float su = shSu[s];
    g_Bl[(b * NC + n0 + nl + 0) * SS + s] = a0 + su * shSc[nl + 0];
    g_Bl[(b * NC + n0 + nl + 1) * SS + s] = a1 + su * shSc[nl + 1];
    g_Bl[(b * NC + n0 + nl + 2) * SS + s] = a2 + su * shSc[nl + 2];
    g_Bl[(b * NC + n0 + nl + 3) * SS + s] = a3 + su * shSc[nl + 3];
}

// ---------------------------------------------------------------------------
// Logit term 3. grid = 128 n * 4 btile = 512; 8 b per block.
// ---------------------------------------------------------------------------
__global__ void __launch_bounds__(256) k_bB() {
    __shared__ float shPE2[SS * 68];  // 34.8 KB
    __shared__ float shV[8 * DD];
    int n  = blockIdx.x >> 2;
    int b0 = (blockIdx.x & 3) * 8;
    for (int idx = threadIdx.x; idx < SS * 16; idx += 256) {
        int s = idx >> 4, c = idx & 15;
        *(float4*)&shPE2[s * 68 + c * 4] = *(const float4*)&g_PE2[s * OD + n * DD + c * 4];
    }
    for (int idx = threadIdx.x; idx < 8 * DD; idx += 256) {
        int bl = idx >> 6, dd = idx & 63;
        shV[idx] = g_V[((b0 + bl) * NC + n) * DD + dd];
    }
    __syncthreads();
    int s = threadIdx.x & 127, h = threadIdx.x >> 7;
    int bl = h * 4;
    const float4* pr = (const float4*)&shPE2[s * 68];
    const float4* v0 = (const float4*)&shV[(bl + 0) * DD];
    const float4* v1 = (const float4*)&shV[(bl + 1) * DD];
    const float4* v2 = (const float4*)&shV[(bl + 2) * DD];
    const float4* v3 = (const float4*)&shV[(bl + 3) * DD];
    float a0 = 0, a1 = 0, a2 = 0, a3 = 0;
    #pragma unroll
    for (int d4 = 0; d4 < 16; d4++) {
        float4 p = pr[d4];
        float4 w0 = v0[d4], w1 = v1[d4], w2 = v2[d4], w3 = v3[d4];
        a0 += p.x * w0.x + p.y * w0.y + p.z * w0.z + p.w * w0.w;
        a1 += p.x * w1.x + p.y * w1.y + p.z * w1.z + p.w * w1.w;
        a2 += p.x * w2.x + p.y * w2.y + p.z * w2.z + p.w * w2.w;
        a3 += p.x * w3.x + p.y * w3.y + p.z * w3.z + p.w * w3.w;
    }
    g_Bl[((b0 + bl + 0) * NC + n) * SS + s] += a0;
    g_Bl[((b0 + bl + 1) * NC + n) * SS + s] += a1;
    g_Bl[((b0 + bl + 2) * NC + n) * SS + s] += a2;
    g_Bl[((b0 + bl + 3) * NC + n) * SS + s] += a3;
}

// ---------------------------------------------------------------------------
// Softmax over n. grid = 32 b * 4 stile = 128, 256 threads (8 warps x 16 n).
// ---------------------------------------------------------------------------
__global__ void __launch_bounds__(256) k_softmax(const float* __restrict__ mask) {
    __shared__ float red[2][8][32];
    int b = blockIdx.x >> 2, s0 = (blockIdx.x & 3) * 32;
    int lane = threadIdx.x & 31, w = threadIdx.x >> 5;
    int s = s0 + lane;
    float v[16];
    float mx = -1e30f;
    #pragma unroll
    for (int j = 0; j < 16; j++) {
        v[j] = g_Bl[(b * NC + w * 16 + j) * SS + s];
        mx = fmaxf(mx, v[j]);
    }
    red[0][w][lane] = mx;
    __syncthreads();
    mx = red[0][0][lane];
    #pragma unroll
    for (int w2 = 1; w2 < 8; w2++) mx = fmaxf(mx, red[0][w2][lane]);
    float sum = 0.f;
    #pragma unroll
    for (int j = 0; j < 16; j++) { v[j] = __expf(v[j] - mx); sum += v[j]; }
    red[1][w][lane] = sum;
    __syncthreads();
    sum = red[1][0][lane];
    #pragma unroll
    for (int w2 = 1; w2 < 8; w2++) sum += red[1][w2][lane];
    float scale = mask[b * SS + s] / sum;
    #pragma unroll
    for (int j = 0; j < 16; j++)
        g_C[(b * NC + w * 16 + j) * SS + s] = v[j] * scale;
}

// ---------------------------------------------------------------------------
extern "C" void kernel_launch(void* const* d_in, const int* in_sizes, int n_in,
                              void* d_out, int out_size) {
    const float* u    = (const float*)d_in[0];
    const float* mask = (const float*)d_in[1];
    const float* W    = (const float*)d_in[2];
    float* out = (float*)d_out;

    k_tables<<<512, 256>>>(mask);
    k_gemmP<<<(BB * SS) / 16, 256>>>(u, W);

    for (int it = 0; it < 3; it++) {
        k_outA<<<512, 256>>>();
        k_outB<<<512, 256>>>(out, it == 2 ? 1 : 0);
        if (it < 2) {
            k_bA<<<512, 256>>>();
            k_bB<<<512, 256>>>();
            k_softmax<<<128, 256>>>(mask);
        }
    }
}

// round 5
// speedup vs baseline: 1.5664x; 1.1487x over previous
#include <cuda_runtime.h>
#include <math.h>

#define BB 32
#define SS 128
#define NC 128
#define DD 64
#define II 256
#define OD 8192   // NC*DD
#define TOFF (BB*NC*DD)

__device__ float g_PE1[NC * DD];
__device__ float g_PE2[SS * OD];        // 4 MB
__device__ float g_P  [BB * SS * DD];
__device__ float g_Su [BB * SS];
__device__ float g_C  [BB * NC * SS];
__device__ float g_T  [2 * BB * NC * DD];
__device__ float g_V  [BB * NC * DD];
__device__ float g_Bl [BB * NC * SS];

// ---------------------------------------------------------------------------
// Merged init: blocks 0..511 = PE tables + initC; blocks 512..767 = gemmP.
// ---------------------------------------------------------------------------
__global__ void __launch_bounds__(256) k_init(const float* __restrict__ u,
                                              const float* __restrict__ W,
                                              const float* __restrict__ mask) {
    __shared__ float shU[16][II];   // used only by gemmP branch
    if (blockIdx.x < 512) {
        // ---- tables + initC ----
        const float LN1E4 = 9.210340371976184f;
        int s = blockIdx.x >> 2;
        int chunk = blockIdx.x & 3;
        int base = chunk * 1024;
        #pragma unroll
        for (int j = 0; j < 4; j++) {
            int k = base + j * 256 + threadIdx.x;
            float invf = __expf(-(float)k * (LN1E4 / 4096.0f));
            float sv, cv;
            __sincosf((float)s * invf, &sv, &cv);
            *(float2*)&g_PE2[s * OD + 2 * k] = make_float2(sv, cv);
        }
        if (chunk == 0 && threadIdx.x < 32) {
            int k = threadIdx.x;
            float invf = __expf(-(float)k * (LN1E4 / 32.0f));
            float sv, cv;
            __sincosf((float)s * invf, &sv, &cv);
            *(float2*)&g_PE1[s * DD + 2 * k] = make_float2(sv, cv);
        }
        for (int idx = blockIdx.x * 256 + threadIdx.x; idx < BB * NC * SS;
             idx += 512 * 256) {
            int s2 = idx & (SS - 1);
            int b  = idx >> 14;
            g_C[idx] = mask[b * SS + s2] * (1.0f / 128.0f);
        }
        return;
    }
    // ---- gemmP: P = u @ W, Su = rowsum(u) ----
    int row0 = (blockIdx.x - 512) * 16;
    for (int idx = threadIdx.x; idx < 16 * 64; idx += 256) {
        int r = idx >> 6, i = idx & 63;
        *(float4*)&shU[r][i * 4] = *(const float4*)&u[(row0 + r) * II + i * 4];
    }
    __syncthreads();
    int d = threadIdx.x & 63, g = threadIdx.x >> 6;
    const float4* u0 = (const float4*)&shU[g][0];
    const float4* u1 = (const float4*)&shU[g + 4][0];
    const float4* u2 = (const float4*)&shU[g + 8][0];
    const float4* u3 = (const float4*)&shU[g + 12][0];
    float a0 = 0, a1 = 0, a2 = 0, a3 = 0;
    #pragma unroll 8
    for (int i4 = 0; i4 < II / 4; i4++) {
        float4 f0 = u0[i4], f1 = u1[i4], f2 = u2[i4], f3 = u3[i4];
        float w0 = __ldg(&W[(i4 * 4 + 0) * DD + d]);
        float w1 = __ldg(&W[(i4 * 4 + 1) * DD + d]);
        float w2 = __ldg(&W[(i4 * 4 + 2) * DD + d]);
        float w3 = __ldg(&W[(i4 * 4 + 3) * DD + d]);
        a0 += f0.x * w0 + f0.y * w1 + f0.z * w2 + f0.w * w3;
        a1 += f1.x * w0 + f1.y * w1 + f1.z * w2 + f1.w * w3;
        a2 += f2.x * w0 + f2.y * w1 + f2.z * w2 + f2.w * w3;
        a3 += f3.x * w0 + f3.y * w1 + f3.z * w2 + f3.w * w3;
    }
    g_P[(row0 + g) * DD + d]      = a0;
    g_P[(row0 + g + 4) * DD + d]  = a1;
    g_P[(row0 + g + 8) * DD + d]  = a2;
    g_P[(row0 + g + 12) * DD + d] = a3;
    int r = threadIdx.x >> 4, t = threadIdx.x & 15;
    float sm = 0.f;
    for (int i = t; i < II; i += 16) sm += shU[r][i];
    sm += __shfl_xor_sync(0xffffffffu, sm, 8);
    sm += __shfl_xor_sync(0xffffffffu, sm, 4);
    sm += __shfl_xor_sync(0xffffffffu, sm, 2);
    sm += __shfl_xor_sync(0xffffffffu, sm, 1);
    if (t == 0) g_Su[row0 + r] = sm;
}

// ---------------------------------------------------------------------------
// Output terms 1+2, s-split halves. grid = 32 b * 8 ntile * 2 half = 512.
// ---------------------------------------------------------------------------
__global__ void __launch_bounds__(256) k_outA() {
    __shared__ float  shP[64 * DD];     // 16 KB
    __shared__ float4 shC4[16 * 16];
    __shared__ float4 shSu4[16];
    int blk  = blockIdx.x;
    int half = blk & 1;
    int n0   = ((blk >> 1) & 7) * 16;
    int b    = blk >> 4;
    int sb   = half * 64;
    for (int idx = threadIdx.x; idx < 64 * 16; idx += 256)
        *(float4*)&shP[idx * 4] = *(const float4*)&g_P[(b * SS + sb) * DD + idx * 4];
    for (int idx = threadIdx.x; idx < 16 * 16; idx += 256) {
        int nr = idx >> 4, sc = idx & 15;
        shC4[idx] = *(const float4*)&g_C[(b * NC + n0 + nr) * SS + sb + sc * 4];
    }
    if (threadIdx.x < 16)
        shSu4[threadIdx.x] = *(const float4*)&g_Su[b * SS + sb + threadIdx.x * 4];
    __syncthreads();
    int d = threadIdx.x & 63, g = threadIdx.x >> 6;
    const float4* c0 = &shC4[(g * 4 + 0) * 16];
    const float4* c1 = &shC4[(g * 4 + 1) * 16];
    const float4* c2 = &shC4[(g * 4 + 2) * 16];
    const float4* c3 = &shC4[(g * 4 + 3) * 16];
    float a0 = 0, a1 = 0, a2 = 0, a3 = 0, q0 = 0, q1 = 0, q2 = 0, q3 = 0;
    #pragma unroll
    for (int s4 = 0; s4 < 16; s4++) {
        float4 f0 = c0[s4], f1 = c1[s4], f2 = c2[s4], f3 = c3[s4];
        float4 su = shSu4[s4];
        float p0 = shP[(s4 * 4 + 0) * DD + d];
        float p1 = shP[(s4 * 4 + 1) * DD + d];
        float p2 = shP[(s4 * 4 + 2) * DD + d];
        float p3 = shP[(s4 * 4 + 3) * DD + d];
        a0 += f0.x * p0 + f0.y * p1 + f0.z * p2 + f0.w * p3;
        a1 += f1.x * p0 + f1.y * p1 + f1.z * p2 + f1.w * p3;
        a2 += f2.x * p0 + f2.y * p1 + f2.z * p2 + f2.w * p3;
        a3 += f3.x * p0 + f3.y * p1 + f3.z * p2 + f3.w * p3;
        q0 += f0.x * su.x + f0.y * su.y + f0.z * su.z + f0.w * su.w;
        q1 += f1.x * su.x + f1.y * su.y + f1.z * su.z + f1.w * su.w;
        q2 += f2.x * su.x + f2.y * su.y + f2.z * su.z + f2.w * su.w;
        q3 += f3.x * su.x + f3.y * su.y + f3.z * su.z + f3.w * su.w;
    }
    int nb = n0 + g * 4;
    float* T = g_T + half * TOFF;
    T[(b * NC + nb + 0) * DD + d] = a0 + q0 * g_PE1[(nb + 0) * DD + d];
    T[(b * NC + nb + 1) * DD + d] = a1 + q1 * g_PE1[(nb + 1) * DD + d];
    T[(b * NC + nb + 2) * DD + d] = a2 + q2 * g_PE1[(nb + 2) * DD + d];
    T[(b * NC + nb + 3) * DD + d] = a3 + q3 * g_PE1[(nb + 3) * DD + d];
}

// ---------------------------------------------------------------------------
// Output term 3 + squash + (fused) logit term 3.
// grid = 128 n * 4 btile = 512; 8 b per block. shPE2 pitched to 68.
// Phase 1: val = T + sum_s c*PE2; V = squash(val)      (thread = (d, b-pair))
// Phase 2: Bl[b,n,s] = sum_d V*PE2                     (thread = (s, b-quad))
// ---------------------------------------------------------------------------
__global__ void __launch_bounds__(256) k_outB(float* __restrict__ dst, int final_) {
    __shared__ float  shPE2[SS * 68];   // 34.8 KB
    __shared__ float4 shC4[8 * 32];
    __shared__ float  shV[8 * DD];      // 2 KB
    __shared__ float  shRed[4][2][2];
    int n  = blockIdx.x >> 2;
    int b0 = (blockIdx.x & 3) * 8;
    float* Vout = final_ ? dst : g_V;
    for (int idx = threadIdx.x; idx < SS * 16; idx += 256) {
        int s = idx >> 4, c = idx & 15;
        *(float4*)&shPE2[s * 68 + c * 4] = *(const float4*)&g_PE2[s * OD + n * DD + c * 4];
    }
    for (int idx = threadIdx.x; idx < 8 * 32; idx += 256) {
        int bl = idx >> 5, sc = idx & 31;
        shC4[idx] = *(const float4*)&g_C[((b0 + bl) * NC + n) * SS + sc * 4];
    }
    __syncthreads();
    int d = threadIdx.x & 63, g = threadIdx.x >> 6;
    int lane = threadIdx.x & 31, wig = (threadIdx.x >> 5) & 1;
    const float4* c0 = &shC4[(g * 2 + 0) * 32];
    const float4* c1 = &shC4[(g * 2 + 1) * 32];
    float a0 = 0, a1 = 0;
    #pragma unroll
    for (int s4 = 0; s4 < 32; s4++) {
        float4 f0 = c0[s4], f1 = c1[s4];
        float p0 = shPE2[(s4 * 4 + 0) * 68 + d];
        float p1 = shPE2[(s4 * 4 + 1) * 68 + d];
        float p2 = shPE2[(s4 * 4 + 2) * 68 + d];
        float p3 = shPE2[(s4 * 4 + 3) * 68 + d];
        a0 += f0.x * p0 + f0.y * p1 + f0.z * p2 + f0.w * p3;
        a1 += f1.x * p0 + f1.y * p1 + f1.z * p2 + f1.w * p3;
    }
    int bA = b0 + g * 2, bBd = bA + 1;
    float val0 = g_T[(bA * NC + n) * DD + d] + g_T[TOFF + (bA * NC + n) * DD + d] + a0;
    float val1 = g_T[(bBd * NC + n) * DD + d] + g_T[TOFF + (bBd * NC + n) * DD + d] + a1;
    float ss0 = val0 * val0, ss1 = val1 * val1;
    #pragma unroll
    for (int off = 16; off; off >>= 1) {
        ss0 += __shfl_xor_sync(0xffffffffu, ss0, off);
        ss1 += __shfl_xor_sync(0xffffffffu, ss1, off);
    }
    if (lane == 0) { shRed[g][wig][0] = ss0; shRed[g][wig][1] = ss1; }
    __syncthreads();
    float t0 = shRed[g][0][0] + shRed[g][1][0];
    float t1 = shRed[g][0][1] + shRed[g][1][1];
    float sc0 = t0 / (1.0f + t0) * rsqrtf(t0 + 1e-7f);
    float sc1 = t1 / (1.0f + t1) * rsqrtf(t1 + 1e-7f);
    float v0w = sc0 * val0, v1w = sc1 * val1;
    Vout[(bA  * NC + n) * DD + d] = v0w;
    Vout[(bBd * NC + n) * DD + d] = v1w;
    if (final_) return;
    shV[(g * 2 + 0) * DD + d] = v0w;
    shV[(g * 2 + 1) * DD + d] = v1w;
    __syncthreads();
    // Phase 2: logit term 3 for this (n, b-tile)
    int s = threadIdx.x & 127, h = threadIdx.x >> 7;
    int bl = h * 4;
    const float4* pr = (const float4*)&shPE2[s * 68];
    const float4* w0 = (const float4*)&shV[(bl + 0) * DD];
    const float4* w1 = (const float4*)&shV[(bl + 1) * DD];
    const float4* w2 = (const float4*)&shV[(bl + 2) * DD];
    const float4* w3 = (const float4*)&shV[(bl + 3) * DD];
    float r0 = 0, r1 = 0, r2 = 0, r3 = 0;
    #pragma unroll
    for (int d4 = 0; d4 < 16; d4++) {
        float4 p = pr[d4];
        float4 x0 = w0[d4], x1 = w1[d4], x2 = w2[d4], x3 = w3[d4];
        r0 += p.x * x0.x + p.y * x0.y + p.z * x0.z + p.w * x0.w;
        r1 += p.x * x1.x + p.y * x1.y + p.z * x1.z + p.w * x1.w;
        r2 += p.x * x2.x + p.y * x2.y + p.z * x2.z + p.w * x2.w;
        r3 += p.x * x3.x + p.y * x3.y + p.z * x3.z + p.w * x3.w;
    }
    g_Bl[((b0 + bl + 0) * NC + n) * SS + s] = r0;
    g_Bl[((b0 + bl + 1) * NC + n) * SS + s] = r1;
    g_Bl[((b0 + bl + 2) * NC + n) * SS + s] = r2;
    g_Bl[((b0 + bl + 3) * NC + n) * SS + s] = r3;
}

// ---------------------------------------------------------------------------
// Logit terms 1+2 (accumulate onto term 3). grid = 32 b * 16 ntile = 512.
// ---------------------------------------------------------------------------
__global__ void __launch_bounds__(256) k_bA() {
    __shared__ float shP[SS * 68];   // 34.8 KB
    __shared__ float shV[8 * DD];
    __shared__ float shSu[SS];
    __shared__ float shSc[8];
    int b  = blockIdx.x >> 4;
    int n0 = (blockIdx.x & 15) * 8;
    for (int idx = threadIdx.x; idx < SS * 16; idx += 256) {
        int s = idx >> 4, c = idx & 15;
        *(float4*)&shP[s * 68 + c * 4] = *(const float4*)&g_P[(b * SS + s) * DD + c * 4];
    }
    for (int idx = threadIdx.x; idx < 8 * 16; idx += 256)
        *(float4*)&shV[idx * 4] = *(const float4*)&g_V[(b * NC + n0) * DD + idx * 4];
    if (threadIdx.x < SS) shSu[threadIdx.x] = g_Su[b * SS + threadIdx.x];
    __syncthreads();
    if (threadIdx.x < 8) {
        int nl = threadIdx.x;
        float t = 0.f;
        for (int dd = 0; dd < DD; dd++) t += shV[nl * DD + dd] * g_PE1[(n0 + nl) * DD + dd];
        shSc[nl] = t;
    }
    __syncthreads();
    int s = threadIdx.x & 127, h = threadIdx.x >> 7;
    int nl = h * 4;
    const float4* pr = (const float4*)&shP[s * 68];
    const float4* v0 = (const float4*)&shV[(nl + 0) * DD];
    const float4* v1 = (const float4*)&shV[(nl + 1) * DD];
    const float4* v2 = (const float4*)&shV[(nl + 2) * DD];
    const float4* v3 = (const float4*)&shV[(nl + 3) * DD];
    float a0 = 0, a1 = 0, a2 = 0, a3 = 0;
    #pragma unroll
    for (int d4 = 0; d4 < 16; d4++) {
        float4 p = pr[d4];
        float4 w0 = v0[d4], w1 = v1[d4], w2 = v2[d4], w3 = v3[d4];
        a0 += p.x * w0.x + p.y * w0.y + p.z * w0.z + p.w * w0.w;
        a1 += p.x * w1.x + p.y * w1.y + p.z * w1.z + p.w * w1.w;
        a2 += p.x * w2.x + p.y * w2.y + p.z * w2.z + p.w * w2.w;
        a3 += p.x * w3.x + p.y * w3.y + p.z * w3.z + p.w * w3.w;
    }
    float su = shSu[s];
    g_Bl[(b * NC + n0 + nl + 0) * SS + s] += a0 + su * shSc[nl + 0];
    g_Bl[(b * NC + n0 + nl + 1) * SS + s] += a1 + su * shSc[nl + 1];
    g_Bl[(b * NC + n0 + nl + 2) * SS + s] += a2 + su * shSc[nl + 2];
    g_Bl[(b * NC + n0 + nl + 3) * SS + s] += a3 + su * shSc[nl + 3];
}

// ---------------------------------------------------------------------------
// Softmax over n. grid = 128, 256 threads (8 warps x 16 n).
// ---------------------------------------------------------------------------
__global__ void __launch_bounds__(256) k_softmax(const float* __restrict__ mask) {
    __shared__ float red[2][8][32];
    int b = blockIdx.x >> 2, s0 = (blockIdx.x & 3) * 32;
    int lane = threadIdx.x & 31, w = threadIdx.x >> 5;
    int s = s0 + lane;
    float v[16];
    float mx = -1e30f;
    #pragma unroll
    for (int j = 0; j < 16; j++) {
        v[j] = g_Bl[(b * NC + w * 16 + j) * SS + s];
        mx = fmaxf(mx, v[j]);
    }
    red[0][w][lane] = mx;
    __syncthreads();
    mx = red[0][0][lane];
    #pragma unroll
    for (int w2 = 1; w2 < 8; w2++) mx = fmaxf(mx, red[0][w2][lane]);
    float sum = 0.f;
    #pragma unroll
    for (int j = 0; j < 16; j++) { v[j] = __expf(v[j] - mx); sum += v[j]; }
    red[1][w][lane] = sum;
    __syncthreads();
    sum = red[1][0][lane];
    #pragma unroll
    for (int w2 = 1; w2 < 8; w2++) sum += red[1][w2][lane];
    float scale = mask[b * SS + s] / sum;
    #pragma unroll
    for (int j = 0; j < 16; j++)
        g_C[(b * NC + w * 16 + j) * SS + s] = v[j] * scale;
}

// ---------------------------------------------------------------------------
extern "C" void kernel_launch(void* const* d_in, const int* in_sizes, int n_in,
                              void* d_out, int out_size) {
    const float* u    = (const float*)d_in[0];
    const float* mask = (const float*)d_in[1];
    const float* W    = (const float*)d_in[2];
    float* out = (float*)d_out;

    k_init<<<768, 256>>>(u, W, mask);

    for (int it = 0; it < 3; it++) {
        k_outA<<<512, 256>>>();
        k_outB<<<512, 256>>>(out, it == 2 ? 1 : 0);
        if (it < 2) {
            k_bA<<<512, 256>>>();
            k_softmax<<<128, 256>>>(mask);
        }
    }
}

// round 7
// speedup vs baseline: 1.6220x; 1.0355x over previous
#include <cuda_runtime.h>
#include <math.h>

#define BB 32
#define SS 128
#define NC 128
#define DD 64
#define II 256
#define OD 8192   // NC*DD
#define TOFF (BB*NC*DD)

__device__ float g_PE1[NC * DD];
__device__ float g_PE2[SS * OD];        // 4 MB
__device__ float g_P  [BB * SS * DD];
__device__ float g_Su [BB * SS];
__device__ float g_C  [BB * NC * SS];
__device__ float g_T  [2 * BB * NC * DD];
__device__ float g_V  [BB * NC * DD];
__device__ float g_Bl [BB * NC * SS];

// ---------------------------------------------------------------------------
// Merged init: blocks 0..511 = PE tables + initC; blocks 512..767 = gemmP.
// ---------------------------------------------------------------------------
__global__ void __launch_bounds__(256) k_init(const float* __restrict__ u,
                                              const float* __restrict__ W,
                                              const float* __restrict__ mask) {
    __shared__ float shU[16][II];   // used only by gemmP branch
    if (blockIdx.x < 512) {
        // ---- tables + initC ----
        const float LN1E4 = 9.210340371976184f;
        int s = blockIdx.x >> 2;
        int chunk = blockIdx.x & 3;
        int base = chunk * 1024;
        #pragma unroll
        for (int j = 0; j < 4; j++) {
            int k = base + j * 256 + threadIdx.x;
            float invf = __expf(-(float)k * (LN1E4 / 4096.0f));
            float sv, cv;
            __sincosf((float)s * invf, &sv, &cv);
            *(float2*)&g_PE2[s * OD + 2 * k] = make_float2(sv, cv);
        }
        if (chunk == 0 && threadIdx.x < 32) {
            int k = threadIdx.x;
            float invf = __expf(-(float)k * (LN1E4 / 32.0f));
            float sv, cv;
            __sincosf((float)s * invf, &sv, &cv);
            *(float2*)&g_PE1[s * DD + 2 * k] = make_float2(sv, cv);
        }
        for (int idx = blockIdx.x * 256 + threadIdx.x; idx < BB * NC * SS;
             idx += 512 * 256) {
            int s2 = idx & (SS - 1);
            int b  = idx >> 14;
            g_C[idx] = mask[b * SS + s2] * (1.0f / 128.0f);
        }
        return;
    }
    // ---- gemmP: P = u @ W, Su = rowsum(u) ----
    int row0 = (blockIdx.x - 512) * 16;
    for (int idx = threadIdx.x; idx < 16 * 64; idx += 256) {
        int r = idx >> 6, i = idx & 63;
        *(float4*)&shU[r][i * 4] = *(const float4*)&u[(row0 + r) * II + i * 4];
    }
    __syncthreads();
    int d = threadIdx.x & 63, g = threadIdx.x >> 6;
    const float4* u0 = (const float4*)&shU[g][0];
    const float4* u1 = (const float4*)&shU[g + 4][0];
    const float4* u2 = (const float4*)&shU[g + 8][0];
    const float4* u3 = (const float4*)&shU[g + 12][0];
    float a0 = 0, a1 = 0, a2 = 0, a3 = 0;
    #pragma unroll 8
    for (int i4 = 0; i4 < II / 4; i4++) {
        float4 f0 = u0[i4], f1 = u1[i4], f2 = u2[i4], f3 = u3[i4];
        float w0 = __ldg(&W[(i4 * 4 + 0) * DD + d]);
        float w1 = __ldg(&W[(i4 * 4 + 1) * DD + d]);
        float w2 = __ldg(&W[(i4 * 4 + 2) * DD + d]);
        float w3 = __ldg(&W[(i4 * 4 + 3) * DD + d]);
        a0 += f0.x * w0 + f0.y * w1 + f0.z * w2 + f0.w * w3;
        a1 += f1.x * w0 + f1.y * w1 + f1.z * w2 + f1.w * w3;
        a2 += f2.x * w0 + f2.y * w1 + f2.z * w2 + f2.w * w3;
        a3 += f3.x * w0 + f3.y * w1 + f3.z * w2 + f3.w * w3;
    }
    g_P[(row0 + g) * DD + d]      = a0;
    g_P[(row0 + g + 4) * DD + d]  = a1;
    g_P[(row0 + g + 8) * DD + d]  = a2;
    g_P[(row0 + g + 12) * DD + d] = a3;
    int r = threadIdx.x >> 4, t = threadIdx.x & 15;
    float sm = 0.f;
    for (int i = t; i < II; i += 16) sm += shU[r][i];
    sm += __shfl_xor_sync(0xffffffffu, sm, 8);
    sm += __shfl_xor_sync(0xffffffffu, sm, 4);
    sm += __shfl_xor_sync(0xffffffffu, sm, 2);
    sm += __shfl_xor_sync(0xffffffffu, sm, 1);
    if (t == 0) g_Su[row0 + r] = sm;
}

// ---------------------------------------------------------------------------
// Output terms 1+2, s-split halves. grid = 32 b * 8 ntile * 2 half = 512.
// ---------------------------------------------------------------------------
__global__ void __launch_bounds__(256) k_outA() {
    __shared__ float  shP[64 * DD];     // 16 KB
    __shared__ float4 shC4[16 * 16];
    __shared__ float4 shSu4[16];
    int blk  = blockIdx.x;
    int half = blk & 1;
    int n0   = ((blk >> 1) & 7) * 16;
    int b    = blk >> 4;
    int sb   = half * 64;
    for (int idx = threadIdx.x; idx < 64 * 16; idx += 256)
        *(float4*)&shP[idx * 4] = *(const float4*)&g_P[(b * SS + sb) * DD + idx * 4];
    for (int idx = threadIdx.x; idx < 16 * 16; idx += 256) {
        int nr = idx >> 4, sc = idx & 15;
        shC4[idx] = *(const float4*)&g_C[(b * NC + n0 + nr) * SS + sb + sc * 4];
    }
    if (threadIdx.x < 16)
        shSu4[threadIdx.x] = *(const float4*)&g_Su[b * SS + sb + threadIdx.x * 4];
    __syncthreads();
    int d = threadIdx.x & 63, g = threadIdx.x >> 6;
    const float4* c0 = &shC4[(g * 4 + 0) * 16];
    const float4* c1 = &shC4[(g * 4 + 1) * 16];
    const float4* c2 = &shC4[(g * 4 + 2) * 16];
    const float4* c3 = &shC4[(g * 4 + 3) * 16];
    float a0 = 0, a1 = 0, a2 = 0, a3 = 0, q0 = 0, q1 = 0, q2 = 0, q3 = 0;
    #pragma unroll
    for (int s4 = 0; s4 < 16; s4++) {
        float4 f0 = c0[s4], f1 = c1[s4], f2 = c2[s4], f3 = c3[s4];
        float4 su = shSu4[s4];
        float p0 = shP[(s4 * 4 + 0) * DD + d];
        float p1 = shP[(s4 * 4 + 1) * DD + d];
        float p2 = shP[(s4 * 4 + 2) * DD + d];
        float p3 = shP[(s4 * 4 + 3) * DD + d];
        a0 += f0.x * p0 + f0.y * p1 + f0.z * p2 + f0.w * p3;
        a1 += f1.x * p0 + f1.y * p1 + f1.z * p2 + f1.w * p3;
        a2 += f2.x * p0 + f2.y * p1 + f2.z * p2 + f2.w * p3;
        a3 += f3.x * p0 + f3.y * p1 + f3.z * p2 + f3.w * p3;
        q0 += f0.x * su.x + f0.y * su.y + f0.z * su.z + f0.w * su.w;
        q1 += f1.x * su.x + f1.y * su.y + f1.z * su.z + f1.w * su.w;
        q2 += f2.x * su.x + f2.y * su.y + f2.z * su.z + f2.w * su.w;
        q3 += f3.x * su.x + f3.y * su.y + f3.z * su.z + f3.w * su.w;
    }
    int nb = n0 + g * 4;
    float* T = g_T + half * TOFF;
    T[(b * NC + nb + 0) * DD + d] = a0 + q0 * g_PE1[(nb + 0) * DD + d];
    T[(b * NC + nb + 1) * DD + d] = a1 + q1 * g_PE1[(nb + 1) * DD + d];
    T[(b * NC + nb + 2) * DD + d] = a2 + q2 * g_PE1[(nb + 2) * DD + d];
    T[(b * NC + nb + 3) * DD + d] = a3 + q3 * g_PE1[(nb + 3) * DD + d];
}

// ---------------------------------------------------------------------------
// Output term 3 + squash + (fused) logit term 3.
// grid = 128 n * 4 btile = 512; 8 b per block. shPE2 pitched to 68.
// ---------------------------------------------------------------------------
__global__ void __launch_bounds__(256) k_outB(float* __restrict__ dst, int final_) {
    __shared__ float  shPE2[SS * 68];   // 34.8 KB
    __shared__ float4 shC4[8 * 32];
    __shared__ float  shV[8 * DD];      // 2 KB
    __shared__ float  shRed[4][2][2];
    int n  = blockIdx.x >> 2;
    int b0 = (blockIdx.x & 3) * 8;
    float* Vout = final_ ? dst : g_V;
    for (int idx = threadIdx.x; idx < SS * 16; idx += 256) {
        int s = idx >> 4, c = idx & 15;
        *(float4*)&shPE2[s * 68 + c * 4] = *(const float4*)&g_PE2[s * OD + n * DD + c * 4];
    }
    for (int idx = threadIdx.x; idx < 8 * 32; idx += 256) {
        int bl = idx >> 5, sc = idx & 31;
        shC4[idx] = *(const float4*)&g_C[((b0 + bl) * NC + n) * SS + sc * 4];
    }
    __syncthreads();
    int d = threadIdx.x & 63, g = threadIdx.x >> 6;
    int lane = threadIdx.x & 31, wig = (threadIdx.x >> 5) & 1;
    const float4* c0 = &shC4[(g * 2 + 0) * 32];
    const float4* c1 = &shC4[(g * 2 + 1) * 32];
    float a0 = 0, a1 = 0;
    #pragma unroll
    for (int s4 = 0; s4 < 32; s4++) {
        float4 f0 = c0[s4], f1 = c1[s4];
        float p0 = shPE2[(s4 * 4 + 0) * 68 + d];
        float p1 = shPE2[(s4 * 4 + 1) * 68 + d];
        float p2 = shPE2[(s4 * 4 + 2) * 68 + d];
        float p3 = shPE2[(s4 * 4 + 3) * 68 + d];
        a0 += f0.x * p0 + f0.y * p1 + f0.z * p2 + f0.w * p3;
        a1 += f1.x * p0 + f1.y * p1 + f1.z * p2 + f1.w * p3;
    }
    int bA = b0 + g * 2, bBd = bA + 1;
    float val0 = g_T[(bA * NC + n) * DD + d] + g_T[TOFF + (bA * NC + n) * DD + d] + a0;
    float val1 = g_T[(bBd * NC + n) * DD + d] + g_T[TOFF + (bBd * NC + n) * DD + d] + a1;
    float ss0 = val0 * val0, ss1 = val1 * val1;
    #pragma unroll
    for (int off = 16; off; off >>= 1) {
        ss0 += __shfl_xor_sync(0xffffffffu, ss0, off);
        ss1 += __shfl_xor_sync(0xffffffffu, ss1, off);
    }
    if (lane == 0) { shRed[g][wig][0] = ss0; shRed[g][wig][1] = ss1; }
    __syncthreads();
    float t0 = shRed[g][0][0] + shRed[g][1][0];
    float t1 = shRed[g][0][1] + shRed[g][1][1];
    float sc0 = t0 / (1.0f + t0) * rsqrtf(t0 + 1e-7f);
    float sc1 = t1 / (1.0f + t1) * rsqrtf(t1 + 1e-7f);
    float v0w = sc0 * val0, v1w = sc1 * val1;
    Vout[(bA  * NC + n) * DD + d] = v0w;
    Vout[(bBd * NC + n) * DD + d] = v1w;
    if (final_) return;
    shV[(g * 2 + 0) * DD + d] = v0w;
    shV[(g * 2 + 1) * DD + d] = v1w;
    __syncthreads();
    // Phase 2: logit term 3 for this (n, b-tile)
    int s = threadIdx.x & 127, h = threadIdx.x >> 7;
    int bl = h * 4;
    const float4* pr = (const float4*)&shPE2[s * 68];
    const float4* w0 = (const float4*)&shV[(bl + 0) * DD];
    const float4* w1 = (const float4*)&shV[(bl + 1) * DD];
    const float4* w2 = (const float4*)&shV[(bl + 2) * DD];
    const float4* w3 = (const float4*)&shV[(bl + 3) * DD];
    float r0 = 0, r1 = 0, r2 = 0, r3 = 0;
    #pragma unroll
    for (int d4 = 0; d4 < 16; d4++) {
        float4 p = pr[d4];
        float4 x0 = w0[d4], x1 = w1[d4], x2 = w2[d4], x3 = w3[d4];
        r0 += p.x * x0.x + p.y * x0.y + p.z * x0.z + p.w * x0.w;
        r1 += p.x * x1.x + p.y * x1.y + p.z * x1.z + p.w * x1.w;
        r2 += p.x * x2.x + p.y * x2.y + p.z * x2.z + p.w * x2.w;
        r3 += p.x * x3.x + p.y * x3.y + p.z * x3.z + p.w * x3.w;
    }
    g_Bl[((b0 + bl + 0) * NC + n) * SS + s] = r0;
    g_Bl[((b0 + bl + 1) * NC + n) * SS + s] = r1;
    g_Bl[((b0 + bl + 2) * NC + n) * SS + s] = r2;
    g_Bl[((b0 + bl + 3) * NC + n) * SS + s] = r3;
}

// ---------------------------------------------------------------------------
// Logit terms 1+2 (accumulate onto term 3). grid = 32 b * 16 ntile = 512.
// shSc computed warp-parallel (one warp per n) — previously an 8-thread
// serial global-load loop that parked the whole block on a barrier.
// ---------------------------------------------------------------------------
__global__ void __launch_bounds__(256) k_bA() {
    __shared__ float shP[SS * 68];   // 34.8 KB
    __shared__ float shV[8 * DD];
    __shared__ float shSu[SS];
    __shared__ float shSc[8];
    int b  = blockIdx.x >> 4;
    int n0 = (blockIdx.x & 15) * 8;
    for (int idx = threadIdx.x; idx < SS * 16; idx += 256) {
        int s = idx >> 4, c = idx & 15;
        *(float4*)&shP[s * 68 + c * 4] = *(const float4*)&g_P[(b * SS + s) * DD + c * 4];
    }
    for (int idx = threadIdx.x; idx < 8 * 16; idx += 256)
        *(float4*)&shV[idx * 4] = *(const float4*)&g_V[(b * NC + n0) * DD + idx * 4];
    if (threadIdx.x < SS) shSu[threadIdx.x] = g_Su[b * SS + threadIdx.x];
    __syncthreads();
    {
        // warp w computes shSc[w] = dot(V[n0+w], PE1[n0+w]); coalesced PE1 loads
        int w = threadIdx.x >> 5, lane = threadIdx.x & 31;
        float t = shV[w * DD + lane]      * g_PE1[(n0 + w) * DD + lane]
                + shV[w * DD + 32 + lane] * g_PE1[(n0 + w) * DD + 32 + lane];
        #pragma unroll
        for (int off = 16; off; off >>= 1)
            t += __shfl_xor_sync(0xffffffffu, t, off);
        if (lane == 0) shSc[w] = t;
    }
    __syncthreads();
    int s = threadIdx.x & 127, h = threadIdx.x >> 7;
    int nl = h * 4;
    const float4* pr = (const float4*)&shP[s * 68];
    const float4* v0 = (const float4*)&shV[(nl + 0) * DD];
    const float4* v1 = (const float4*)&shV[(nl + 1) * DD];
    const float4* v2 = (const float4*)&shV[(nl + 2) * DD];
    const float4* v3 = (const float4*)&shV[(nl + 3) * DD];
    float a0 = 0, a1 = 0, a2 = 0, a3 = 0;
    #pragma unroll
    for (int d4 = 0; d4 < 16; d4++) {
        float4 p = pr[d4];
        float4 w0 = v0[d4], w1 = v1[d4], w2 = v2[d4], w3 = v3[d4];
        a0 += p.x * w0.x + p.y * w0.y + p.z * w0.z + p.w * w0.w;
        a1 += p.x * w1.x + p.y * w1.y + p.z * w1.z + p.w * w1.w;
        a2 += p.x * w2.x + p.y * w2.y + p.z * w2.z + p.w * w2.w;
        a3 += p.x * w3.x + p.y * w3.y + p.z * w3.z + p.w * w3.w;
    }
    float su = shSu[s];
    g_Bl[(b * NC + n0 + nl + 0) * SS + s] += a0 + su * shSc[nl + 0];
    g_Bl[(b * NC + n0 + nl + 1) * SS + s] += a1 + su * shSc[nl + 1];
    g_Bl[(b * NC + n0 + nl + 2) * SS + s] += a2 + su * shSc[nl + 2];
    g_Bl[(b * NC + n0 + nl + 3) * SS + s] += a3 + su * shSc[nl + 3];
}

// ---------------------------------------------------------------------------
// Softmax over n. grid = 128, 256 threads (8 warps x 16 n).
// ---------------------------------------------------------------------------
__global__ void __launch_bounds__(256) k_softmax(const float* __restrict__ mask) {
    __shared__ float red[2][8][32];
    int b = blockIdx.x >> 2, s0 = (blockIdx.x & 3) * 32;
    int lane = threadIdx.x & 31, w = threadIdx.x >> 5;
    int s = s0 + lane;
    float v[16];
    float mx = -1e30f;
    #pragma unroll
    for (int j = 0; j < 16; j++) {
        v[j] = g_Bl[(b * NC + w * 16 + j) * SS + s];
        mx = fmaxf(mx, v[j]);
    }
    red[0][w][lane] = mx;
    __syncthreads();
    mx = red[0][0][lane];
    #pragma unroll
    for (int w2 = 1; w2 < 8; w2++) mx = fmaxf(mx, red[0][w2][lane]);
    float sum = 0.f;
    #pragma unroll
    for (int j = 0; j < 16; j++) { v[j] = __expf(v[j] - mx); sum += v[j]; }
    red[1][w][lane] = sum;
    __syncthreads();
    sum = red[1][0][lane];
    #pragma unroll
    for (int w2 = 1; w2 < 8; w2++) sum += red[1][w2][lane];
    float scale = mask[b * SS + s] / sum;
    #pragma unroll
    for (int j = 0; j < 16; j++)
        g_C[(b * NC + w * 16 + j) * SS + s] = v[j] * scale;
}

// ---------------------------------------------------------------------------
extern "C" void kernel_launch(void* const* d_in, const int* in_sizes, int n_in,
                              void* d_out, int out_size) {
    const float* u    = (const float*)d_in[0];
    const float* mask = (const float*)d_in[1];
    const float* W    = (const float*)d_in[2];
    float* out = (float*)d_out;

    k_init<<<768, 256>>>(u, W, mask);

    for (int it = 0; it < 3; it++) {
        k_outA<<<512, 256>>>();
        k_outB<<<512, 256>>>(out, it == 2 ? 1 : 0);
        if (it < 2) {
            k_bA<<<512, 256>>>();
            k_softmax<<<128, 256>>>(mask);
        }
    }
}